// round 4
// baseline (speedup 1.0000x reference)
#include <cuda_runtime.h>

#define BATCH      16384
#define FIELD_DIM  100000

// scratch: per-row [s1(32) | s2(16)] block sums, 48 floats/row
__device__ float g_scratch[BATCH * 48];

// ---------------------------------------------------------------------------
// Kernel A: pure gather + segment-sum. ONE row per warp, no loop, no smem.
// ---------------------------------------------------------------------------
__global__ __launch_bounds__(256) void gather_kernel(
    const int*   __restrict__ x,    // [B, 26]
    const float* __restrict__ t0,   // [800000, 64]
    const float* __restrict__ t1,   // [800000, 32]
    const float* __restrict__ t2,   // [1000000, 16]
    float*       __restrict__ out)  // [B, 64]  (block0 sum, no bias)
{
    const int warp = threadIdx.x >> 5;
    const int lane = threadIdx.x & 31;
    const unsigned FULL = 0xffffffffu;
    const int row = blockIdx.x * 8 + warp;          // grid 2048 x 8 warps = 16384

    int myidx = 0;
    if (lane < 26) myidx = x[row * 26 + lane];

    // ---- all gathers issued back-to-back (max MLP) ----
    float2 v0[8];
    #pragma unroll
    for (int f = 0; f < 8; f++) {
        int idx = __shfl_sync(FULL, myidx, f) + f * FIELD_DIM;
        v0[f] = ((const float2*)(t0 + (long long)idx * 64))[lane];     // 256B/warp
    }
    float v1[8];
    #pragma unroll
    for (int f = 0; f < 8; f++) {
        int idx = __shfl_sync(FULL, myidx, 8 + f) + f * FIELD_DIM;
        v1[f] = t1[(long long)idx * 32 + lane];                        // 128B/warp
    }
    const int half = lane >> 4;
    const int l16  = lane & 15;
    float v2[5];
    #pragma unroll
    for (int p = 0; p < 5; p++) {
        int f = 2 * p + half;
        int idx = __shfl_sync(FULL, myidx, 16 + f) + f * FIELD_DIM;
        v2[p] = t2[(long long)idx * 16 + l16];                         // 2 rows / 128B
    }

    // ---- reductions ----
    float2 acc = make_float2(0.f, 0.f);
    #pragma unroll
    for (int f = 0; f < 8; f++) { acc.x += v0[f].x; acc.y += v0[f].y; }

    float s1 = 0.f;
    #pragma unroll
    for (int f = 0; f < 8; f++) s1 += v1[f];

    float s2 = 0.f;
    #pragma unroll
    for (int p = 0; p < 5; p++) s2 += v2[p];
    s2 += __shfl_xor_sync(FULL, s2, 16);

    // ---- coalesced stores ----
    ((float2*)(out + (long long)row * 64))[lane] = acc;
    g_scratch[row * 48 + lane] = s1;
    if (lane < 16) g_scratch[row * 48 + 32 + lane] = s2;
}

// ---------------------------------------------------------------------------
// Kernel B: out += S[B,48] @ Wt[48,64] + bias.  32 rows/block, 4 rows/warp.
// ---------------------------------------------------------------------------
__global__ __launch_bounds__(256) void proj_kernel(
    const float* __restrict__ W1,   // [64, 32]
    const float* __restrict__ b1,   // [64]
    const float* __restrict__ W2,   // [64, 16]
    const float* __restrict__ b2,   // [64]
    float*       __restrict__ out)  // [B, 64]
{
    __shared__ float2 sW[48 * 32];      // sW[k*32+l] = {W[2l][k], W[2l+1][k]}
    __shared__ float2 sBias[32];
    __shared__ float  sS[32 * 48];      // this block's 32 rows of S

    const int tid = threadIdx.x;

    #pragma unroll
    for (int i = tid; i < 48 * 32; i += 256) {
        int k = i >> 5, l = i & 31;
        float a, b;
        if (k < 32) { a = W1[(2 * l) * 32 + k];        b = W1[(2 * l + 1) * 32 + k]; }
        else        { a = W2[(2 * l) * 16 + (k - 32)]; b = W2[(2 * l + 1) * 16 + (k - 32)]; }
        sW[i] = make_float2(a, b);
    }
    if (tid < 32)
        sBias[tid] = make_float2(8.f * b1[2 * tid]     + 10.f * b2[2 * tid],
                                 8.f * b1[2 * tid + 1] + 10.f * b2[2 * tid + 1]);

    // coalesced copy: 32 rows x 48 floats = 384 float4
    {
        const float4* src = (const float4*)(g_scratch + (long long)blockIdx.x * 32 * 48);
        float4* dst = (float4*)sS;
        #pragma unroll
        for (int i = tid; i < 384; i += 256) dst[i] = src[i];
    }
    __syncthreads();

    const int warp = tid >> 5;
    const int lane = tid & 31;
    const int row0 = blockIdx.x * 32 + warp * 4;

    float2 acc[4];
    const float2 bias = sBias[lane];
    #pragma unroll
    for (int r = 0; r < 4; r++) {
        float2 p = ((const float2*)(out + (long long)(row0 + r) * 64))[lane];
        acc[r] = make_float2(p.x + bias.x, p.y + bias.y);
    }

    #pragma unroll
    for (int k4 = 0; k4 < 12; k4++) {
        float4 s4[4];
        #pragma unroll
        for (int r = 0; r < 4; r++)
            s4[r] = *(const float4*)&sS[(warp * 4 + r) * 48 + k4 * 4];  // uniform bcast

        #pragma unroll
        for (int j = 0; j < 4; j++) {
            float2 w = sW[(k4 * 4 + j) * 32 + lane];
            #pragma unroll
            for (int r = 0; r < 4; r++) {
                float sv = (j == 0) ? s4[r].x : (j == 1) ? s4[r].y
                         : (j == 2) ? s4[r].z : s4[r].w;
                acc[r].x += w.x * sv;
                acc[r].y += w.y * sv;
            }
        }
    }

    #pragma unroll
    for (int r = 0; r < 4; r++)
        ((float2*)(out + (long long)(row0 + r) * 64))[lane] = acc[r];
}

extern "C" void kernel_launch(void* const* d_in, const int* in_sizes, int n_in,
                              void* d_out, int out_size)
{
    const int*   x  = (const int*)  d_in[0];
    const float* t0 = (const float*)d_in[1];
    const float* t1 = (const float*)d_in[2];
    const float* t2 = (const float*)d_in[3];
    const float* W1 = (const float*)d_in[4];
    const float* b1 = (const float*)d_in[5];
    const float* W2 = (const float*)d_in[6];
    const float* b2 = (const float*)d_in[7];
    float* out = (float*)d_out;

    gather_kernel<<<BATCH / 8, 256>>>(x, t0, t1, t2, out);     // 2048 blocks
    proj_kernel<<<BATCH / 32, 256>>>(W1, b1, W2, b2, out);     // 512 blocks
}

// round 5
// speedup vs baseline: 1.3617x; 1.3617x over previous
#include <cuda_runtime.h>

#define BATCH      16384
#define FIELD_DIM  100000

// scratch: per-row [s1(32) | s2(16)] block sums, 48 floats/row
__device__ float  g_scratch[BATCH * 48];
// pre-transposed weights: g_wT[k*32+l] = {W[2l][k], W[2l+1][k]} (k<32: W1, else W2)
__device__ float2 g_wT[48 * 32];
__device__ float2 g_bias[32];

// ---------------------------------------------------------------------------
// Kernel A: gather + segment-sum (blocks 0..2047, one row per warp).
// Block 2048 instead transposes W into g_wT (hidden under gather latency).
// ---------------------------------------------------------------------------
__global__ __launch_bounds__(256) void gather_kernel(
    const int*   __restrict__ x,    // [B, 26]
    const float* __restrict__ t0,   // [800000, 64]
    const float* __restrict__ t1,   // [800000, 32]
    const float* __restrict__ t2,   // [1000000, 16]
    const float* __restrict__ W1,   // [64, 32]
    const float* __restrict__ b1,   // [64]
    const float* __restrict__ W2,   // [64, 16]
    const float* __restrict__ b2,   // [64]
    float*       __restrict__ out)  // [B, 64]  (block0 sum, no bias)
{
    const int tid = threadIdx.x;

    if (blockIdx.x == BATCH / 8) {
        // ---- one-time W transpose + bias fold ----
        #pragma unroll
        for (int i = tid; i < 48 * 32; i += 256) {
            int k = i >> 5, l = i & 31;
            float a, b;
            if (k < 32) { a = W1[(2 * l) * 32 + k];        b = W1[(2 * l + 1) * 32 + k]; }
            else        { a = W2[(2 * l) * 16 + (k - 32)]; b = W2[(2 * l + 1) * 16 + (k - 32)]; }
            g_wT[i] = make_float2(a, b);
        }
        if (tid < 32)
            g_bias[tid] = make_float2(8.f * b1[2 * tid]     + 10.f * b2[2 * tid],
                                      8.f * b1[2 * tid + 1] + 10.f * b2[2 * tid + 1]);
        return;
    }

    const int warp = tid >> 5;
    const int lane = tid & 31;
    const unsigned FULL = 0xffffffffu;
    const int row = blockIdx.x * 8 + warp;

    int myidx = 0;
    if (lane < 26) myidx = x[row * 26 + lane];

    // ---- all gathers issued back-to-back (max MLP) ----
    float2 v0[8];
    #pragma unroll
    for (int f = 0; f < 8; f++) {
        int idx = __shfl_sync(FULL, myidx, f) + f * FIELD_DIM;
        v0[f] = ((const float2*)(t0 + (long long)idx * 64))[lane];     // 256B/warp
    }
    float v1[8];
    #pragma unroll
    for (int f = 0; f < 8; f++) {
        int idx = __shfl_sync(FULL, myidx, 8 + f) + f * FIELD_DIM;
        v1[f] = t1[(long long)idx * 32 + lane];                        // 128B/warp
    }
    const int half = lane >> 4;
    const int l16  = lane & 15;
    float v2[5];
    #pragma unroll
    for (int p = 0; p < 5; p++) {
        int f = 2 * p + half;
        int idx = __shfl_sync(FULL, myidx, 16 + f) + f * FIELD_DIM;
        v2[p] = t2[(long long)idx * 16 + l16];                         // 2 rows / 128B
    }

    // ---- reductions ----
    float2 acc = make_float2(0.f, 0.f);
    #pragma unroll
    for (int f = 0; f < 8; f++) { acc.x += v0[f].x; acc.y += v0[f].y; }

    float s1 = 0.f;
    #pragma unroll
    for (int f = 0; f < 8; f++) s1 += v1[f];

    float s2 = 0.f;
    #pragma unroll
    for (int p = 0; p < 5; p++) s2 += v2[p];
    s2 += __shfl_xor_sync(FULL, s2, 16);

    // ---- coalesced stores ----
    ((float2*)(out + (long long)row * 64))[lane] = acc;
    g_scratch[row * 48 + lane] = s1;
    if (lane < 16) g_scratch[row * 48 + 32 + lane] = s2;
}

// ---------------------------------------------------------------------------
// Kernel B: out += S[B,48] @ Wt[48,64] + bias.  32 rows/block, 4 rows/warp.
// W already transposed in gmem -> fully coalesced staging.
// ---------------------------------------------------------------------------
__global__ __launch_bounds__(256) void proj_kernel(float* __restrict__ out)
{
    __shared__ float2 sW[48 * 32];
    __shared__ float2 sBias[32];
    __shared__ float  sS[32 * 48];

    const int tid = threadIdx.x;

    // coalesced: 1536 float2 = 768 float4, 3 per thread
    {
        const float4* src = (const float4*)g_wT;
        float4* dst = (float4*)sW;
        #pragma unroll
        for (int i = tid; i < 768; i += 256) dst[i] = src[i];
    }
    if (tid < 32) sBias[tid] = g_bias[tid];

    // coalesced: 32 rows x 48 floats = 384 float4
    {
        const float4* src = (const float4*)(g_scratch + (long long)blockIdx.x * 32 * 48);
        float4* dst = (float4*)sS;
        #pragma unroll
        for (int i = tid; i < 384; i += 256) dst[i] = src[i];
    }
    __syncthreads();

    const int warp = tid >> 5;
    const int lane = tid & 31;
    const int row0 = blockIdx.x * 32 + warp * 4;

    float2 acc[4];
    const float2 bias = sBias[lane];
    #pragma unroll
    for (int r = 0; r < 4; r++) {
        float2 p = ((const float2*)(out + (long long)(row0 + r) * 64))[lane];
        acc[r] = make_float2(p.x + bias.x, p.y + bias.y);
    }

    #pragma unroll
    for (int k4 = 0; k4 < 12; k4++) {
        float4 s4[4];
        #pragma unroll
        for (int r = 0; r < 4; r++)
            s4[r] = *(const float4*)&sS[(warp * 4 + r) * 48 + k4 * 4];  // uniform bcast

        #pragma unroll
        for (int j = 0; j < 4; j++) {
            float2 w = sW[(k4 * 4 + j) * 32 + lane];
            #pragma unroll
            for (int r = 0; r < 4; r++) {
                float sv = (j == 0) ? s4[r].x : (j == 1) ? s4[r].y
                         : (j == 2) ? s4[r].z : s4[r].w;
                acc[r].x += w.x * sv;
                acc[r].y += w.y * sv;
            }
        }
    }

    #pragma unroll
    for (int r = 0; r < 4; r++)
        ((float2*)(out + (long long)(row0 + r) * 64))[lane] = acc[r];
}

extern "C" void kernel_launch(void* const* d_in, const int* in_sizes, int n_in,
                              void* d_out, int out_size)
{
    const int*   x  = (const int*)  d_in[0];
    const float* t0 = (const float*)d_in[1];
    const float* t1 = (const float*)d_in[2];
    const float* t2 = (const float*)d_in[3];
    const float* W1 = (const float*)d_in[4];
    const float* b1 = (const float*)d_in[5];
    const float* W2 = (const float*)d_in[6];
    const float* b2 = (const float*)d_in[7];
    float* out = (float*)d_out;

    gather_kernel<<<BATCH / 8 + 1, 256>>>(x, t0, t1, t2, W1, b1, W2, b2, out);
    proj_kernel<<<BATCH / 32, 256>>>(out);
}